// round 14
// baseline (speedup 1.0000x reference)
#include <cuda_runtime.h>
#include <math.h>

// ---------------------------------------------------------------------------
// SE4: 4x4-patch squeeze-excite. Proven R3 kernel bodies + software-pipelined
// two-stream schedule:
//   sA: pool(A) ; pool(B) ; gate(A) ; gate(B)      (DRAM-bound, back-to-back)
//   sB:   mlp(A) under pool(B) ; mlp(B) under gate(A)
// Event edges: mlp(X) waits pool(X); gate(X) waits mlp(X). The MLP latency
// (~6.5us serial) is hidden behind the other half's DRAM traffic.
// Streams/events created at static init (outside capture, no device allocs).
// ---------------------------------------------------------------------------

#define B_   8
#define C_   64
#define H_   256
#define W_   256
#define SQ_  256
#define GC_  1024
#define NPOOL (B_ * GC_)
#define NT   256
#define BATCH_F4 (C_ * H_ * W_ / 4)       // 2^20 float4 per batch
#define HALF_B 4

__device__ float g_pooled[NPOOL];
__device__ float g_s[B_ * SQ_];
__device__ float g_gates[NPOOL];

// ---------------------------------------------------------------------------
__device__ __forceinline__ float mishf(float x) {
    float sp = (x > 20.0f) ? x : log1pf(__expf(x));
    return x * tanhf(sp);
}
__device__ __forceinline__ float sigmoidf_(float x) {
    return 1.0f / (1.0f + __expf(-x));
}

// ---------------------------------------------------------------------------
// Pool: one warp per full 64x64 patch. Half grid = 4*1024/8 = 512 blocks.
// ---------------------------------------------------------------------------
__global__ void __launch_bounds__(NT) se4_pool(const float* __restrict__ t, int b0) {
    int warp = blockIdx.x * 8 + (threadIdx.x >> 5);
    int lane = threadIdx.x & 31;

    int b  = b0 + (warp >> 10);
    int r  = warp & 1023;
    int c  = r >> 4;
    int ij = r & 15;
    int i  = ij >> 2;
    int j  = ij & 3;

    const float* base = t + (((size_t)(b * C_ + c) * H_ + i * 64) * W_ + j * 64);
    const float* p = base + (size_t)(lane >> 4) * W_ + (lane & 15) * 4;

    float a0 = 0.f, a1 = 0.f, a2 = 0.f, a3 = 0.f;
#pragma unroll
    for (int it = 0; it < 8; ++it) {
        float4 v0 = *reinterpret_cast<const float4*>(p + (size_t)(it * 8 + 0) * W_);
        float4 v1 = *reinterpret_cast<const float4*>(p + (size_t)(it * 8 + 2) * W_);
        float4 v2 = *reinterpret_cast<const float4*>(p + (size_t)(it * 8 + 4) * W_);
        float4 v3 = *reinterpret_cast<const float4*>(p + (size_t)(it * 8 + 6) * W_);
        a0 += (v0.x + v0.y) + (v0.z + v0.w);
        a1 += (v1.x + v1.y) + (v1.z + v1.w);
        a2 += (v2.x + v2.y) + (v2.z + v2.w);
        a3 += (v3.x + v3.y) + (v3.z + v3.w);
    }
    float acc = (a0 + a1) + (a2 + a3);
#pragma unroll
    for (int off = 16; off > 0; off >>= 1)
        acc += __shfl_down_sync(0xFFFFFFFFu, acc, off);

    if (lane == 0)
        g_pooled[b * GC_ + ij * C_ + c] = acc * (1.0f / 4096.0f);
}

// ---------------------------------------------------------------------------
// mlp1: one warp per (b,out). Half grid = 4*256/8 = 128 blocks.
// ---------------------------------------------------------------------------
__global__ void __launch_bounds__(NT) se4_mlp1(const float* __restrict__ reduce_w,
                                               const float* __restrict__ reduce_b,
                                               int b0) {
    int lw   = blockIdx.x * 8 + (threadIdx.x >> 5);
    int lane = threadIdx.x & 31;
    int b    = b0 + (lw >> 8);
    int out  = lw & 255;

    const float4* wrow = reinterpret_cast<const float4*>(reduce_w + (size_t)out * GC_);
    const float4* prow = reinterpret_cast<const float4*>(g_pooled + (size_t)b * GC_);

    float acc = 0.0f;
#pragma unroll
    for (int k4 = lane; k4 < GC_ / 4; k4 += 32) {
        float4 wv = wrow[k4];
        float4 pv = prow[k4];
        acc += wv.x * pv.x + wv.y * pv.y + wv.z * pv.z + wv.w * pv.w;
    }
#pragma unroll
    for (int off = 16; off > 0; off >>= 1)
        acc += __shfl_down_sync(0xFFFFFFFFu, acc, off);
    if (lane == 0)
        g_s[b * SQ_ + out] = mishf(acc + reduce_b[out]);
}

// ---------------------------------------------------------------------------
// mlp2: one warp per (b,out). Half grid = 4*1024/8 = 512 blocks.
// ---------------------------------------------------------------------------
__global__ void __launch_bounds__(NT) se4_mlp2(const float* __restrict__ expand_w,
                                               const float* __restrict__ expand_b,
                                               int b0) {
    int lw   = blockIdx.x * 8 + (threadIdx.x >> 5);
    int lane = threadIdx.x & 31;
    int b    = b0 + (lw >> 10);
    int out  = lw & 1023;

    const float4* wrow = reinterpret_cast<const float4*>(expand_w + (size_t)out * SQ_);
    const float4* srow = reinterpret_cast<const float4*>(g_s + (size_t)b * SQ_);

    float acc = 0.0f;
#pragma unroll
    for (int k4 = lane; k4 < SQ_ / 4; k4 += 32) {
        float4 wv = wrow[k4];
        float4 sv = srow[k4];
        acc += wv.x * sv.x + wv.y * sv.y + wv.z * sv.z + wv.w * sv.w;
    }
#pragma unroll
    for (int off = 16; off > 0; off >>= 1)
        acc += __shfl_down_sync(0xFFFFFFFFu, acc, off);
    if (lane == 0)
        g_gates[b * GC_ + out] = sigmoidf_(acc + expand_b[out]);
}

// ---------------------------------------------------------------------------
// Gate: one consecutive float4 per thread. Half grid = 16384 blocks.
// Reads .cs, writes .stcs.
// ---------------------------------------------------------------------------
__global__ void __launch_bounds__(NT) se4_gate(const float* __restrict__ t,
                                               float* __restrict__ out,
                                               int b0) {
    size_t idx4 = (size_t)blockIdx.x * NT + threadIdx.x;   // within half
    int w4 = (int)(idx4 & 63);
    int h  = (int)(idx4 >> 6) & 255;
    int c  = (int)(idx4 >> 14) & 63;
    int bl = (int)(idx4 >> 20);

    float gate = __ldg(&g_gates[(b0 + bl) * GC_ + (h >> 6) * 256 + (w4 >> 4) * 64 + c]);

    const float4* tb = reinterpret_cast<const float4*>(t)  + (size_t)b0 * BATCH_F4;
    float4*       ob = reinterpret_cast<float4*>(out)      + (size_t)b0 * BATCH_F4;

    float4 v = __ldcs(tb + idx4);
    v.x *= gate; v.y *= gate; v.z *= gate; v.w *= gate;
    __stcs(ob + idx4, v);
}

// ---------------------------------------------------------------------------
// Static streams/events (created at load time, outside capture, no allocs).
// ---------------------------------------------------------------------------
static cudaStream_t g_sA = nullptr, g_sB = nullptr;
static cudaEvent_t  g_evRoot = nullptr;
static cudaEvent_t  g_evPA = nullptr, g_evPB = nullptr;   // pool done
static cudaEvent_t  g_evMA = nullptr, g_evMB = nullptr;   // mlp done
static cudaEvent_t  g_evEnd = nullptr;
static bool g_forkOK = false;

namespace {
struct SE4Init {
    SE4Init() {
        bool ok = true;
        ok &= (cudaStreamCreateWithFlags(&g_sA, cudaStreamNonBlocking) == cudaSuccess);
        ok &= (cudaStreamCreateWithFlags(&g_sB, cudaStreamNonBlocking) == cudaSuccess);
        ok &= (cudaEventCreateWithFlags(&g_evRoot, cudaEventDisableTiming) == cudaSuccess);
        ok &= (cudaEventCreateWithFlags(&g_evPA,  cudaEventDisableTiming) == cudaSuccess);
        ok &= (cudaEventCreateWithFlags(&g_evPB,  cudaEventDisableTiming) == cudaSuccess);
        ok &= (cudaEventCreateWithFlags(&g_evMA,  cudaEventDisableTiming) == cudaSuccess);
        ok &= (cudaEventCreateWithFlags(&g_evMB,  cudaEventDisableTiming) == cudaSuccess);
        ok &= (cudaEventCreateWithFlags(&g_evEnd, cudaEventDisableTiming) == cudaSuccess);
        g_forkOK = ok;
    }
};
SE4Init g_se4_init;
}

// ---------------------------------------------------------------------------
extern "C" void kernel_launch(void* const* d_in, const int* in_sizes, int n_in,
                              void* d_out, int out_size) {
    const float* t        = (const float*)d_in[0];
    const float* reduce_w = (const float*)d_in[1];
    const float* reduce_b = (const float*)d_in[2];
    const float* expand_w = (const float*)d_in[3];
    const float* expand_b = (const float*)d_in[4];
    float* out = (float*)d_out;

    if (g_forkOK) {
        // Fork from the capture-origin stream.
        cudaEventRecord(g_evRoot, 0);
        cudaStreamWaitEvent(g_sA, g_evRoot, 0);
        cudaStreamWaitEvent(g_sB, g_evRoot, 0);

        // sA: DRAM-bound chain, back-to-back.
        se4_pool<<<HALF_B * 128, NT, 0, g_sA>>>(t, 0);
        cudaEventRecord(g_evPA, g_sA);
        se4_pool<<<HALF_B * 128, NT, 0, g_sA>>>(t, HALF_B);
        cudaEventRecord(g_evPB, g_sA);

        // sB: mlp(A) under pool(B).
        cudaStreamWaitEvent(g_sB, g_evPA, 0);
        se4_mlp1<<<HALF_B * 32,  NT, 0, g_sB>>>(reduce_w, reduce_b, 0);
        se4_mlp2<<<HALF_B * 128, NT, 0, g_sB>>>(expand_w, expand_b, 0);
        cudaEventRecord(g_evMA, g_sB);

        // sA: gate(A) after mlp(A).
        cudaStreamWaitEvent(g_sA, g_evMA, 0);
        se4_gate<<<HALF_B * 4096, NT, 0, g_sA>>>(t, out, 0);

        // sB: mlp(B) under gate(A).
        cudaStreamWaitEvent(g_sB, g_evPB, 0);
        se4_mlp1<<<HALF_B * 32,  NT, 0, g_sB>>>(reduce_w, reduce_b, HALF_B);
        se4_mlp2<<<HALF_B * 128, NT, 0, g_sB>>>(expand_w, expand_b, HALF_B);
        cudaEventRecord(g_evMB, g_sB);

        // sA: gate(B) after mlp(B).
        cudaStreamWaitEvent(g_sA, g_evMB, 0);
        se4_gate<<<HALF_B * 4096, NT, 0, g_sA>>>(t, out, HALF_B);

        // Join back into the origin stream.
        cudaEventRecord(g_evEnd, g_sA);
        cudaStreamWaitEvent(0, g_evEnd, 0);
    } else {
        // Serial fallback (round-3 structure).
        se4_pool<<<1024, NT>>>(t, 0);           // both halves via two launches
        se4_pool<<<1024, NT>>>(t, HALF_B);
        se4_mlp1<<<256,  NT>>>(reduce_w, reduce_b, 0);
        se4_mlp2<<<1024, NT>>>(expand_w, expand_b, 0);
        se4_mlp1<<<256,  NT>>>(reduce_w, reduce_b, HALF_B);
        se4_mlp2<<<1024, NT>>>(expand_w, expand_b, HALF_B);
        se4_gate<<<16384, NT>>>(t, out, 0);
        se4_gate<<<16384, NT>>>(t, out, HALF_B);
    }
}

// round 15
// speedup vs baseline: 1.1202x; 1.1202x over previous
#include <cuda_runtime.h>
#include <math.h>

// ---------------------------------------------------------------------------
// SE4: 4x4-patch squeeze-excite. Round-3 serial structure (proven optimum):
//   pool ; mlp1 ; mlp2 ; gate     (4 launches, full-width grids)
// Gate upgraded: each thread handles TWO fully-coalesced float4 at idx4 and
// idx4 + 4*2^20 (same (c,h,w), batches b and b+4) -> 2x memory-level
// parallelism, one shared index computation, half the blocks.
// ---------------------------------------------------------------------------

#define B_   8
#define C_   64
#define H_   256
#define W_   256
#define SQ_  256
#define GC_  1024
#define NPOOL (B_ * GC_)
#define NT   256
#define BATCH_F4 (C_ * H_ * W_ / 4)       // 2^20 float4 per batch
#define HALF_F4 (4 * BATCH_F4)            // 4 batches of float4

__device__ float g_pooled[NPOOL];
__device__ float g_s[B_ * SQ_];
__device__ float g_gates[NPOOL];

// ---------------------------------------------------------------------------
__device__ __forceinline__ float mishf(float x) {
    float sp = (x > 20.0f) ? x : log1pf(__expf(x));
    return x * tanhf(sp);
}
__device__ __forceinline__ float sigmoidf_(float x) {
    return 1.0f / (1.0f + __expf(-x));
}

// ---------------------------------------------------------------------------
// Kernel 1: patch mean pool (exact round-1 body, 73% DRAM). One warp per
// (b,c,i,j) patch; 8192 warps = 1024 blocks x 256 threads.
// ---------------------------------------------------------------------------
__global__ void __launch_bounds__(NT) se4_pool(const float* __restrict__ t) {
    int warp = blockIdx.x * 8 + (threadIdx.x >> 5);
    int lane = threadIdx.x & 31;

    int b  = warp >> 10;
    int r  = warp & 1023;
    int c  = r >> 4;
    int ij = r & 15;
    int i  = ij >> 2;
    int j  = ij & 3;

    const float* base = t + (((size_t)(b * C_ + c) * H_ + i * 64) * W_ + j * 64);
    int row0 = lane >> 4;           // 0 or 1
    int col4 = lane & 15;           // 0..15

    float acc = 0.0f;
#pragma unroll 8
    for (int it = 0; it < 32; ++it) {
        int row = it * 2 + row0;
        float4 v = *reinterpret_cast<const float4*>(base + (size_t)row * W_ + col4 * 4);
        acc += (v.x + v.y) + (v.z + v.w);
    }
#pragma unroll
    for (int off = 16; off > 0; off >>= 1)
        acc += __shfl_down_sync(0xFFFFFFFFu, acc, off);

    if (lane == 0)
        g_pooled[b * GC_ + ij * C_ + c] = acc * (1.0f / 4096.0f);
}

// ---------------------------------------------------------------------------
// Kernel 2a: s = mish(pooled @ reduce_w^T + b). One warp per (b,out).
// 2048 warps = 256 blocks.
// ---------------------------------------------------------------------------
__global__ void __launch_bounds__(NT) se4_mlp1(const float* __restrict__ reduce_w,
                                               const float* __restrict__ reduce_b) {
    int warp = blockIdx.x * 8 + (threadIdx.x >> 5);
    int lane = threadIdx.x & 31;
    int b    = warp >> 8;
    int out  = warp & 255;

    const float4* wrow = reinterpret_cast<const float4*>(reduce_w + (size_t)out * GC_);
    const float4* prow = reinterpret_cast<const float4*>(g_pooled + (size_t)b * GC_);

    float acc = 0.0f;
#pragma unroll
    for (int k4 = lane; k4 < GC_ / 4; k4 += 32) {
        float4 wv = wrow[k4];
        float4 pv = prow[k4];
        acc += wv.x * pv.x + wv.y * pv.y + wv.z * pv.z + wv.w * pv.w;
    }
#pragma unroll
    for (int off = 16; off > 0; off >>= 1)
        acc += __shfl_down_sync(0xFFFFFFFFu, acc, off);
    if (lane == 0)
        g_s[b * SQ_ + out] = mishf(acc + reduce_b[out]);
}

// ---------------------------------------------------------------------------
// Kernel 2b: g = sigmoid(s @ expand_w^T + b). One warp per (b,out).
// 8192 warps = 1024 blocks.
// ---------------------------------------------------------------------------
__global__ void __launch_bounds__(NT) se4_mlp2(const float* __restrict__ expand_w,
                                               const float* __restrict__ expand_b) {
    int warp = blockIdx.x * 8 + (threadIdx.x >> 5);
    int lane = threadIdx.x & 31;
    int b    = warp >> 10;
    int out  = warp & 1023;

    const float4* wrow = reinterpret_cast<const float4*>(expand_w + (size_t)out * SQ_);
    const float4* srow = reinterpret_cast<const float4*>(g_s + (size_t)b * SQ_);

    float acc = 0.0f;
#pragma unroll
    for (int k4 = lane; k4 < SQ_ / 4; k4 += 32) {
        float4 wv = wrow[k4];
        float4 sv = srow[k4];
        acc += wv.x * sv.x + wv.y * sv.y + wv.z * sv.z + wv.w * sv.w;
    }
#pragma unroll
    for (int off = 16; off > 0; off >>= 1)
        acc += __shfl_down_sync(0xFFFFFFFFu, acc, off);
    if (lane == 0)
        g_gates[b * GC_ + out] = sigmoidf_(acc + expand_b[out]);
}

// ---------------------------------------------------------------------------
// Kernel 3: gating, 2 elements per thread. Thread handles idx4 (batches 0-3)
// and idx4 + HALF_F4 (same c/h/w, batches 4-7; gate offset is +4*GC_).
// grid = HALF_F4 / NT = 16384 blocks. Reads .cs, writes .stcs.
// ---------------------------------------------------------------------------
__global__ void __launch_bounds__(NT) se4_gate(const float* __restrict__ t,
                                               float* __restrict__ out) {
    size_t idx4 = (size_t)blockIdx.x * NT + threadIdx.x;   // in [0, HALF_F4)
    int w4 = (int)(idx4 & 63);
    int h  = (int)(idx4 >> 6) & 255;
    int c  = (int)(idx4 >> 14) & 63;
    int b  = (int)(idx4 >> 20);                            // 0..3

    const float* gp = &g_gates[b * GC_ + (h >> 6) * 256 + (w4 >> 4) * 64 + c];
    float gate0 = __ldg(gp);
    float gate1 = __ldg(gp + 4 * GC_);

    const float4* t4 = reinterpret_cast<const float4*>(t);
    float4*       o4 = reinterpret_cast<float4*>(out);

    float4 v0 = __ldcs(t4 + idx4);
    float4 v1 = __ldcs(t4 + idx4 + HALF_F4);
    v0.x *= gate0; v0.y *= gate0; v0.z *= gate0; v0.w *= gate0;
    v1.x *= gate1; v1.y *= gate1; v1.z *= gate1; v1.w *= gate1;
    __stcs(o4 + idx4,           v0);
    __stcs(o4 + idx4 + HALF_F4, v1);
}

// ---------------------------------------------------------------------------
extern "C" void kernel_launch(void* const* d_in, const int* in_sizes, int n_in,
                              void* d_out, int out_size) {
    const float* t        = (const float*)d_in[0];
    const float* reduce_w = (const float*)d_in[1];
    const float* reduce_b = (const float*)d_in[2];
    const float* expand_w = (const float*)d_in[3];
    const float* expand_b = (const float*)d_in[4];
    float* out = (float*)d_out;

    se4_pool<<<1024, NT>>>(t);
    se4_mlp1<<<256, NT>>>(reduce_w, reduce_b);
    se4_mlp2<<<1024, NT>>>(expand_w, expand_b);
    se4_gate<<<16384, NT>>>(t, out);
}